// round 3
// baseline (speedup 1.0000x reference)
#include <cuda_runtime.h>
#include <cstdint>

#define B_    2
#define NH_   8
#define N_    4096
#define D_    64
#define K2_   49
#define V_F4  784          // D*K2/4
#define THREADS 128
#define ROWS  16           // rows per CTA (16 | 4096 so h constant per CTA)
#define STAGES 3

__device__ __forceinline__ uint32_t smem_u32(const void* p) {
    return (uint32_t)__cvta_generic_to_shared(p);
}
__device__ __forceinline__ void cp16(uint32_t dst, const void* src) {
    asm volatile("cp.async.cg.shared.global [%0], [%1], 16;\n" :: "r"(dst), "l"(src));
}
__device__ __forceinline__ void cp4(uint32_t dst, const void* src) {
    asm volatile("cp.async.ca.shared.global [%0], [%1], 4;\n" :: "r"(dst), "l"(src));
}
__device__ __forceinline__ void cp_commit() {
    asm volatile("cp.async.commit_group;\n" ::: "memory");
}
template <int NPend>
__device__ __forceinline__ void cp_wait() {
    asm volatile("cp.async.wait_group %0;\n" :: "n"(NPend) : "memory");
}

struct __align__(16) Stage {
    float4 v[V_F4];        // 12544 B
    float  q[D_];          // 256 B
    float  al[K2_];        // 196 B
    float  b[K2_];         // 196 B
    float  pad[2];         // 8 B -> sizeof = 13200, 16B multiple
};

__global__ __launch_bounds__(THREADS)
void sw_attention_av_pipe3(const float* __restrict__ q_norm,      // [B,NH,N,D]
                           const float* __restrict__ attn_local,  // [B,NH,N,K2]
                           const float* __restrict__ v_local,     // [B,NH,N,D,K2]
                           const float* __restrict__ tokens,      // [NH,D,K2]
                           const float* __restrict__ bias,        // [NH,N,K2]
                           float* __restrict__ out)               // [B,NH,N,D]
{
    __shared__ Stage st[STAGES];
    __shared__ float s_attn[K2_ + 1];   // [49] = 0 pad for branch-free phase 2

    const int t    = threadIdx.x;
    const int row0 = blockIdx.x * ROWS;
    const int h    = (row0 >> 12) & (NH_ - 1);
    const float* tok_h = tokens + h * (D_ * K2_);

    auto prefetch = [&](int s, int row) {
        const float4* vrow = reinterpret_cast<const float4*>(v_local) + (size_t)row * V_F4;
        uint32_t vdst = smem_u32(st[s].v);
#pragma unroll
        for (int i = 0; i < 6; i++)
            cp16(vdst + (uint32_t)(t + THREADS * i) * 16u, vrow + t + THREADS * i);
        if (t < V_F4 - 6 * THREADS)                          // 16 leftover
            cp16(vdst + (uint32_t)(t + 6 * THREADS) * 16u, vrow + t + 6 * THREADS);

        if (t < D_ / 4)
            cp16(smem_u32(st[s].q) + (uint32_t)t * 16u,
                 reinterpret_cast<const float4*>(q_norm + (size_t)row * D_) + t);

        if (t < K2_) {
            const int n = row & (N_ - 1);
            cp4(smem_u32(st[s].al) + (uint32_t)t * 4u, attn_local + (size_t)row * K2_ + t);
            cp4(smem_u32(st[s].b)  + (uint32_t)t * 4u, bias + ((size_t)h * N_ + n) * K2_ + t);
        }
        cp_commit();
    };

    if (t == 0) s_attn[K2_] = 0.f;       // pad (never rewritten)

    // prologue: two rows in flight
    prefetch(0, row0);
    prefetch(1, row0 + 1);

    for (int r = 0; r < ROWS; r++) {
        // keep 2 groups in flight during the compute of row r
        if (r + 2 < ROWS) { prefetch((r + 2) % STAGES, row0 + r + 2); cp_wait<2>(); }
        else if (r + 2 == ROWS) cp_wait<1>();
        else cp_wait<0>();
        __syncthreads();                                      // A: stage r%S ready

        const Stage& S = st[r % STAGES];

        // ---- phase 1 (all 128 threads): attn[k] = q . tokens[:,k] + bias + al
        {
            int k  = t >> 1;                 // 0..63
            bool valid = (k < K2_);          // t < 98
            int kk = valid ? k : K2_ - 1;
            int d0 = (t & 1) << 5;           // 0 or 32
            const float* tk = tok_h + kk;
            float a = 0.f;
#pragma unroll
            for (int d = 0; d < 32; d++)
                a = fmaf(S.q[d0 + d], __ldg(tk + (size_t)(d0 + d) * K2_), a);
            a += __shfl_xor_sync(0xFFFFFFFFu, a, 1);          // pair lanes combine
            if (valid && !(t & 1))
                s_attn[k] = a + S.b[k] + S.al[k];
        }
        __syncthreads();                                      // B: s_attn ready

        // ---- phase 2 (all 128 threads): out[d] = sum_k attn[k] * v[d,k]
        {
            int d     = t >> 1;              // 0..63
            int start = (t & 1) * 25;        // 0..24 / 25..49 (s_attn[49]=0)
            const float* vd = reinterpret_cast<const float*>(S.v) + d * K2_ + start;
            const float* ak = s_attn + start;
            float acc = 0.f;
#pragma unroll
            for (int j = 0; j < 25; j++)
                acc = fmaf(ak[j], vd[j], acc);
            acc += __shfl_xor_sync(0xFFFFFFFFu, acc, 1);
            if (!(t & 1))
                __stcs(out + (size_t)(row0 + r) * D_ + d, acc);
        }
        __syncthreads();                     // C: readers of stage (r-?)%S done
    }
}

extern "C" void kernel_launch(void* const* d_in, const int* in_sizes, int n_in,
                              void* d_out, int out_size)
{
    const float* q_norm     = (const float*)d_in[0];
    const float* attn_local = (const float*)d_in[1];
    const float* v_local    = (const float*)d_in[2];
    const float* tokens     = (const float*)d_in[3];
    const float* bias       = (const float*)d_in[4];
    float* out = (float*)d_out;

    const int blocks = (B_ * NH_ * N_) / ROWS;   // 4096
    sw_attention_av_pipe3<<<blocks, THREADS>>>(q_norm, attn_local, v_local,
                                               tokens, bias, out);
}